// round 15
// baseline (speedup 1.0000x reference)
#include <cuda_runtime.h>
#include <cuda_bf16.h>
#include <cstdint>

#define N_NODES 100000
#define N_EDGES 1600000
#define IN_CH   17
#define HID     64
#define BATCH   10000
#define BN_EPS  1e-5f
#define NSCAN_B 391

typedef unsigned long long ull;

// ---------------- device scratch ----------------
__device__ float g_h  [(size_t)N_NODES * HID];
__device__ float g_msg[(size_t)N_NODES * HID];   // accumulates T = sum of tanh
__device__ float g_P  [(size_t)N_NODES * 128];   // per-node GEMM1 precompute (stage-2)
__device__ float g_P12[(size_t)N_NODES * 68];    // stage-1 precompute
__device__ int   g_cnt[N_NODES];                 // in-degree (int)
__device__ int   g_cur[N_NODES];                 // scatter cursors
__device__ int   g_bsum[NSCAN_B];
__device__ int   g_boff[NSCAN_B];
__device__ float g_rdeg[N_NODES];
__device__ float g_stats[4 * 128];
__device__ float g_z1[BATCH * 64];
__device__ float g_z2[BATCH * 32];
__device__ int   g_src[N_EDGES];
__device__ int   g_dst[N_EDGES];
__device__ int   g_dst2[N_EDGES];                // sorted by dst
__device__ int2  g_sd2[N_EDGES];                 // (src, dts-bits) sorted by dst
// pre-packed bf16 hi/lo weight images (W^T row-major [n][k], row stride 144B)
__device__ __align__(16) unsigned char g_BPhi[128 * 144];
__device__ __align__(16) unsigned char g_BPlo[128 * 144];
__device__ __align__(16) unsigned char g_B2hi[64 * 144];
__device__ __align__(16) unsigned char g_B2lo[64 * 144];

__device__ __forceinline__ float tanh_fast(float x) {
    float e = __expf(2.f * x);
    return 1.f - __fdividef(2.f, e + 1.f);
}
__device__ __forceinline__ ull pack2(float x) {
    ull r; asm("mov.b64 %0,{%1,%1};" : "=l"(r) : "f"(x)); return r;
}
__device__ __forceinline__ void unpack2(ull a, float& x, float& y) {
    asm("mov.b64 {%0,%1},%2;" : "=f"(x), "=f"(y) : "l"(a));
}
__device__ __forceinline__ void fma2(ull& d, ull a, ull b) {
    asm("fma.rn.f32x2 %0,%1,%2,%0;" : "+l"(d) : "l"(a), "l"(b));
}
__device__ __forceinline__ ull add2(ull a, ull b) {
    ull r; asm("add.rn.f32x2 %0,%1,%2;" : "=l"(r) : "l"(a), "l"(b)); return r;
}
__device__ __forceinline__ void red4(float* p, float a, float b, float c, float d) {
    asm volatile("{\n\t.reg .u64 q;\n\tcvta.to.global.u64 q,%0;\n\t"
                 "red.global.add.v4.f32 [q],{%1,%2,%3,%4};\n\t}"
                 :: "l"(p), "f"(a), "f"(b), "f"(c), "f"(d) : "memory");
}
__device__ __forceinline__ void red2(float* p, float a, float b) {
    asm volatile("{\n\t.reg .u64 q;\n\tcvta.to.global.u64 q,%0;\n\t"
                 "red.global.add.v2.f32 [q],{%1,%2};\n\t}"
                 :: "l"(p), "f"(a), "f"(b) : "memory");
}
__device__ __forceinline__ void pf_l1(const void* p) {
    asm volatile("prefetch.global.L1 [%0];" :: "l"(p));
}
__device__ __forceinline__ uint32_t smem_u32(const void* p) {
    uint32_t a;
    asm("{.reg .u64 t; cvta.to.shared.u64 t, %1; cvt.u32.u64 %0, t;}" : "=r"(a) : "l"(p));
    return a;
}
__device__ __forceinline__ void ldx4(uint32_t* r, uint32_t a) {
    asm volatile("ldmatrix.sync.aligned.m8n8.x4.shared.b16 {%0,%1,%2,%3}, [%4];"
                 : "=r"(r[0]), "=r"(r[1]), "=r"(r[2]), "=r"(r[3]) : "r"(a));
}
__device__ __forceinline__ void mma16816(float* d, const uint32_t* a, uint32_t b0, uint32_t b1) {
    asm volatile("mma.sync.aligned.m16n8k16.row.col.f32.bf16.bf16.f32 "
                 "{%0,%1,%2,%3},{%4,%5,%6,%7},{%8,%9},{%0,%1,%2,%3};"
                 : "+f"(d[0]), "+f"(d[1]), "+f"(d[2]), "+f"(d[3])
                 : "r"(a[0]), "r"(a[1]), "r"(a[2]), "r"(a[3]), "r"(b0), "r"(b1));
}
__device__ __forceinline__ void split2(float x, float y, uint32_t& hi, uint32_t& lo) {
    __nv_bfloat162 h = __float22bfloat162_rn(make_float2(x, y));
    float2 hf = __bfloat1622float2(h);
    __nv_bfloat162 l = __float22bfloat162_rn(make_float2(x - hf.x, y - hf.y));
    hi = *(uint32_t*)&h; lo = *(uint32_t*)&l;
}

// ---------------- zero scratch ----------------
__global__ void k_zero_all() {
    int i = blockIdx.x * 256 + threadIdx.x;
    int st = gridDim.x * 256;
    float4 z = make_float4(0.f, 0.f, 0.f, 0.f);
    float4* m4 = (float4*)g_msg;
    for (int k = i; k < N_NODES * HID / 4; k += st) m4[k] = z;
    for (int k = i; k < N_NODES; k += st) g_cnt[k] = 0;
    if (i < 512) g_stats[i] = 0.f;
}

// ---------------- stage-1 node precompute ----------------
__global__ __launch_bounds__(256)
void k_pre1(const float* __restrict__ x, const float* __restrict__ W1,
            const float* __restrict__ b1) {
    __shared__ float sW[34 * 36];
    __shared__ __align__(8) float sB[34];
    int tid = threadIdx.x;
    for (int i = tid; i < 34 * 33; i += 256) {
        int r = i / 33, c = i - r * 33;
        sW[r * 36 + c] = W1[i];
    }
    if (tid < 33) sB[tid] = b1[tid];
    if (tid == 33) sB[33] = 0.f;
    __syncthreads();

    int n = blockIdx.x * 128 + (tid >> 1);
    int q = tid & 1;
    if (n >= N_NODES) return;

    ull acc[16];
    float t;
    if (q == 0) {
        const ull* bp = (const ull*)sB;
#pragma unroll
        for (int p = 0; p < 16; p++) acc[p] = bp[p];
        t = sB[32];
    } else {
#pragma unroll
        for (int p = 0; p < 16; p++) acc[p] = 0ull;
        t = 0.f;
    }

    const float* xp = x + (size_t)n * IN_CH;
#pragma unroll 1
    for (int i = 0; i < 17; i++) {
        float v = xp[i];
        ull m = pack2(v);
        const ulonglong2* wp = (const ulonglong2*)(sW + (17 * q + i) * 36);
#pragma unroll
        for (int h = 0; h < 8; h++) {
            ulonglong2 w = wp[h];
            fma2(acc[2 * h], m, w.x);
            fma2(acc[2 * h + 1], m, w.y);
        }
        t = fmaf(v, sW[(17 * q + i) * 36 + 32], t);
    }

    float* P = g_P12 + (size_t)n * 68 + 34 * q;
#pragma unroll
    for (int p = 0; p < 16; p++) {
        float a, b;
        unpack2(acc[p], a, b);
        *(float2*)(P + 2 * p) = make_float2(a, b);
    }
    P[32] = t;
}

// ---------------- edge index conversion + int degree ----------------
__global__ void k_convert_idx(const void* __restrict__ ei_raw) {
    __shared__ int s_is64;
    if (threadIdx.x == 0) {
        const unsigned* w = (const unsigned*)ei_raw;
        int is64 = 1;
        for (int i = 1; i < 64; i += 2)
            if (w[i] != 0u) { is64 = 0; break; }
        s_is64 = is64;
    }
    __syncthreads();
    int e = blockIdx.x * 256 + threadIdx.x;
    if (e >= N_EDGES) return;
    int s, d;
    if (s_is64) {
        const long long* p = (const long long*)ei_raw;
        s = (int)p[e]; d = (int)p[(size_t)N_EDGES + e];
    } else {
        const int* p = (const int*)ei_raw;
        s = p[e]; d = p[N_EDGES + e];
    }
    g_src[e] = s; g_dst[e] = d;
    atomicAdd(&g_cnt[d], 1);
}

// ---------------- 3-phase scan ----------------
__global__ __launch_bounds__(256)
void k_scan1() {
    __shared__ int sp[8];
    int n = blockIdx.x * 256 + threadIdx.x;
    int v = (n < N_NODES) ? g_cnt[n] : 0;
#pragma unroll
    for (int o = 16; o > 0; o >>= 1) v += __shfl_down_sync(0xFFFFFFFFu, v, o);
    if ((threadIdx.x & 31) == 0) sp[threadIdx.x >> 5] = v;
    __syncthreads();
    if (threadIdx.x == 0) {
        int s = 0;
#pragma unroll
        for (int i = 0; i < 8; i++) s += sp[i];
        g_bsum[blockIdx.x] = s;
    }
}
__global__ __launch_bounds__(512)
void k_scan2() {
    __shared__ int arr[512];
    int t = threadIdx.x;
    int v = (t < NSCAN_B) ? g_bsum[t] : 0;
    arr[t] = v;
    __syncthreads();
#pragma unroll
    for (int d = 1; d < 512; d <<= 1) {
        int u = (t >= d) ? arr[t - d] : 0;
        __syncthreads();
        arr[t] += u;
        __syncthreads();
    }
    if (t < NSCAN_B) g_boff[t] = arr[t] - v;
}
__global__ __launch_bounds__(256)
void k_scan3() {
    __shared__ int arr[256];
    int t = threadIdx.x;
    int n = blockIdx.x * 256 + t;
    int v = (n < N_NODES) ? g_cnt[n] : 0;
    arr[t] = v;
    __syncthreads();
#pragma unroll
    for (int d = 1; d < 256; d <<= 1) {
        int u = (t >= d) ? arr[t - d] : 0;
        __syncthreads();
        arr[t] += u;
        __syncthreads();
    }
    if (n < N_NODES) {
        g_cur[n] = g_boff[blockIdx.x] + arr[t] - v;
        g_rdeg[n] = 1.f / fmaxf((float)v, 1.f);
    }
}

// ---------------- scatter edges into dst-sorted order ----------------
__global__ void k_scatter(const float* __restrict__ dts) {
    int e = blockIdx.x * 256 + threadIdx.x;
    if (e >= N_EDGES) return;
    int d = g_dst[e];
    int pos = atomicAdd(&g_cur[d], 1);
    g_dst2[pos] = d;
    g_sd2[pos] = make_int2(g_src[e], __float_as_int(dts[e]));
}

// ---------------- stage 1: paired consecutive edges; merge REDs when same dst ----
__global__ __launch_bounds__(256)
void k_stage1(const float* __restrict__ bf, const float* __restrict__ ph,
              const float* __restrict__ W1,
              const float* __restrict__ W2, const float* __restrict__ b2) {
    __shared__ float sW1[32 * 36];
    __shared__ float sW2[33 * 20];
    __shared__ __align__(16) float sB2[18], sF[32], sP[32];
    int tid = threadIdx.x;
    for (int i = tid; i < 32 * 33; i += 256) {
        int r = i / 33, c = i - r * 33;
        sW1[r * 36 + c] = W1[(34 + r) * 33 + c];
    }
    for (int i = tid; i < 33 * 17; i += 256) {
        int r = i / 17, c = i - r * 17;
        sW2[r * 20 + c] = W2[i];
    }
    if (tid < 17) sB2[tid] = b2[tid];
    if (tid < 32) { sF[tid] = bf[tid]; sP[tid] = ph[tid]; }
    __syncthreads();

    int idx = blockIdx.x * 256 + tid;
    int e0 = idx * 2, e1 = idx * 2 + 1;
    int2 sd0 = g_sd2[e0], sd1 = g_sd2[e1];
    int d0 = g_dst2[e0], d1 = g_dst2[e1];
    int s0 = sd0.x, s1 = sd1.x;
    float dt0 = __int_as_float(sd0.y), dt1 = __int_as_float(sd1.y);

    ull a0[16], a1[16];
    float t0, t1;
    {
        const ull* p1d0 = (const ull*)(g_P12 + (size_t)d0 * 68);
        const ull* p2s0 = (const ull*)(g_P12 + (size_t)s0 * 68 + 34);
        const ull* p1d1 = (const ull*)(g_P12 + (size_t)d1 * 68);
        const ull* p2s1 = (const ull*)(g_P12 + (size_t)s1 * 68 + 34);
#pragma unroll
        for (int p = 0; p < 16; p++) {
            a0[p] = add2(p1d0[p], p2s0[p]);
            a1[p] = add2(p1d1[p], p2s1[p]);
        }
        t0 = g_P12[(size_t)d0 * 68 + 32] + g_P12[(size_t)s0 * 68 + 66];
        t1 = g_P12[(size_t)d1 * 68 + 32] + g_P12[(size_t)s1 * 68 + 66];
    }

#pragma unroll 1
    for (int t = 0; t < 32; t++) {
        float f = sF[t], p = sP[t];
        float v0 = __cosf(dt0 * f + p);
        float v1 = __cosf(dt1 * f + p);
        ull m0 = pack2(v0), m1 = pack2(v1);
        const ulonglong2* wp = (const ulonglong2*)(sW1 + t * 36);
        ulonglong2 wa = wp[0], wb = wp[1], wc = wp[2], wd = wp[3];
        ulonglong2 we = wp[4], wf2 = wp[5], wg = wp[6], wh = wp[7];
        fma2(a0[0], m0, wa.x);  fma2(a1[0], m1, wa.x);
        fma2(a0[1], m0, wa.y);  fma2(a1[1], m1, wa.y);
        fma2(a0[2], m0, wb.x);  fma2(a1[2], m1, wb.x);
        fma2(a0[3], m0, wb.y);  fma2(a1[3], m1, wb.y);
        fma2(a0[4], m0, wc.x);  fma2(a1[4], m1, wc.x);
        fma2(a0[5], m0, wc.y);  fma2(a1[5], m1, wc.y);
        fma2(a0[6], m0, wd.x);  fma2(a1[6], m1, wd.x);
        fma2(a0[7], m0, wd.y);  fma2(a1[7], m1, wd.y);
        fma2(a0[8], m0, we.x);  fma2(a1[8], m1, we.x);
        fma2(a0[9], m0, we.y);  fma2(a1[9], m1, we.y);
        fma2(a0[10], m0, wf2.x); fma2(a1[10], m1, wf2.x);
        fma2(a0[11], m0, wf2.y); fma2(a1[11], m1, wf2.y);
        fma2(a0[12], m0, wg.x); fma2(a1[12], m1, wg.x);
        fma2(a0[13], m0, wg.y); fma2(a1[13], m1, wg.y);
        fma2(a0[14], m0, wh.x); fma2(a1[14], m1, wh.x);
        fma2(a0[15], m0, wh.y); fma2(a1[15], m1, wh.y);
        float ws = sW1[t * 36 + 32];
        t0 = fmaf(v0, ws, t0); t1 = fmaf(v1, ws, t1);
    }

    float h0[33], h1[33];
#pragma unroll
    for (int p = 0; p < 16; p++) {
        unpack2(a0[p], h0[2 * p], h0[2 * p + 1]);
        unpack2(a1[p], h1[2 * p], h1[2 * p + 1]);
    }
    h0[32] = t0; h1[32] = t1;
#pragma unroll
    for (int i = 0; i < 33; i++) { h0[i] = fmaxf(h0[i], 0.f); h1[i] = fmaxf(h1[i], 0.f); }

    ull c0[8], c1[8]; float q0, q1;
    {
        const ull* bp = (const ull*)sB2;
#pragma unroll
        for (int p = 0; p < 8; p++) { c0[p] = bp[p]; c1[p] = bp[p]; }
        q0 = sB2[16]; q1 = sB2[16];
    }
#pragma unroll 1
    for (int i = 0; i < 33; i++) {
        ull m0 = pack2(h0[i]), m1 = pack2(h1[i]);
        const ulonglong2* wp = (const ulonglong2*)(sW2 + i * 20);
        ulonglong2 wa = wp[0], wb = wp[1], wc = wp[2], wd = wp[3];
        fma2(c0[0], m0, wa.x); fma2(c1[0], m1, wa.x);
        fma2(c0[1], m0, wa.y); fma2(c1[1], m1, wa.y);
        fma2(c0[2], m0, wb.x); fma2(c1[2], m1, wb.x);
        fma2(c0[3], m0, wb.y); fma2(c1[3], m1, wb.y);
        fma2(c0[4], m0, wc.x); fma2(c1[4], m1, wc.x);
        fma2(c0[5], m0, wc.y); fma2(c1[5], m1, wc.y);
        fma2(c0[6], m0, wd.x); fma2(c1[6], m1, wd.x);
        fma2(c0[7], m0, wd.y); fma2(c1[7], m1, wd.y);
        float ws = sW2[i * 20 + 16];
        q0 = fmaf(h0[i], ws, q0); q1 = fmaf(h1[i], ws, q1);
    }

    float pv0[17], pv1[17];
#pragma unroll
    for (int p = 0; p < 8; p++) {
        unpack2(c0[p], pv0[2 * p], pv0[2 * p + 1]);
        unpack2(c1[p], pv1[2 * p], pv1[2 * p + 1]);
    }
    pv0[16] = q0; pv1[16] = q1;

    if (d0 == d1) {
        float m[17];
#pragma unroll
        for (int j = 0; j < 17; j++) m[j] = tanh_fast(pv0[j]) + tanh_fast(pv1[j]);
        float* base = g_msg + (size_t)d0 * 64;
        red4(base + 0, m[0], m[1], m[2], m[3]);
        red4(base + 4, m[4], m[5], m[6], m[7]);
        red4(base + 8, m[8], m[9], m[10], m[11]);
        red4(base + 12, m[12], m[13], m[14], m[15]);
        atomicAdd(base + 16, m[16]);
    } else {
        float m[17];
#pragma unroll
        for (int j = 0; j < 17; j++) m[j] = tanh_fast(pv0[j]);
        float* base = g_msg + (size_t)d0 * 64;
        red4(base + 0, m[0], m[1], m[2], m[3]);
        red4(base + 4, m[4], m[5], m[6], m[7]);
        red4(base + 8, m[8], m[9], m[10], m[11]);
        red4(base + 12, m[12], m[13], m[14], m[15]);
        atomicAdd(base + 16, m[16]);
#pragma unroll
        for (int j = 0; j < 17; j++) m[j] = tanh_fast(pv1[j]);
        base = g_msg + (size_t)d1 * 64;
        red4(base + 0, m[0], m[1], m[2], m[3]);
        red4(base + 4, m[4], m[5], m[6], m[7]);
        red4(base + 8, m[8], m[9], m[10], m[11]);
        red4(base + 12, m[12], m[13], m[14], m[15]);
        atomicAdd(base + 16, m[16]);
    }
}

// ---------------- node update + projection ----------------
__global__ __launch_bounds__(256)
void k_proj(const float* __restrict__ x, const float* __restrict__ PW,
            const float* __restrict__ Pb) {
    __shared__ float sW[17 * 64];
    __shared__ __align__(16) float sB[64];
    int tid = threadIdx.x;
    for (int i = tid; i < 17 * 64; i += 256) sW[i] = PW[i];
    if (tid < 64) sB[tid] = Pb[tid];
    __syncthreads();

    int n = blockIdx.x * 128 + (tid >> 1);
    int q = tid & 1;
    if (n >= N_NODES) return;
    float rdeg = g_rdeg[n];
    float cnt = (float)g_cnt[n];

    ull acc[16];
    {
        const ull* bp = (const ull*)(sB + 32 * q);
#pragma unroll
        for (int p = 0; p < 16; p++) acc[p] = bp[p];
    }

    const float* xp = x + (size_t)n * 17;
    float* mp = g_msg + (size_t)n * 64;

#pragma unroll 1
    for (int k = 0; k < 17; k++) {
        float fac = 1.f + rdeg * (2.f * mp[k] - cnt);
        float xm = xp[k] * fac;
        ull m = pack2(xm);
        const ulonglong2* wp = (const ulonglong2*)(sW + k * 64 + 32 * q);
#pragma unroll
        for (int h = 0; h < 8; h++) {
            ulonglong2 w = wp[h];
            fma2(acc[2 * h], m, w.x);
            fma2(acc[2 * h + 1], m, w.y);
        }
    }

    float* hp = g_h + (size_t)n * 64 + 32 * q;
#pragma unroll
    for (int h = 0; h < 8; h++) {
        float a, b2, c, d;
        unpack2(acc[2 * h], a, b2);
        unpack2(acc[2 * h + 1], c, d);
        *(float4*)(hp + 4 * h) = make_float4(a, b2, c, d);
    }
    if (q == 0) {
        float4 z = make_float4(0.f, 0.f, 0.f, 0.f);
        *(float4*)(mp + 0) = z; *(float4*)(mp + 4) = z;
        *(float4*)(mp + 8) = z; *(float4*)(mp + 12) = z;
        mp[16] = 0.f;
    }
}

// ---------------- weight prep ----------------
__global__ void k_prep_w(const float* __restrict__ W1, const float* __restrict__ W2) {
    int idx = blockIdx.x * 256 + threadIdx.x;
    if (idx < 8192) {
        int nn = idx >> 6, k = idx & 63;
        float w = (nn < 64) ? W1[k * 64 + nn] : W1[(64 + k) * 64 + (nn - 64)];
        __nv_bfloat16 h = __float2bfloat16_rn(w);
        __nv_bfloat16 l = __float2bfloat16_rn(w - __bfloat162float(h));
        uint32_t off = (uint32_t)nn * 144u + 2u * (uint32_t)k;
        *(__nv_bfloat16*)(g_BPhi + off) = h;
        *(__nv_bfloat16*)(g_BPlo + off) = l;
    }
    if (idx < 4096) {
        int n = idx >> 6, k = idx & 63;
        float w = W2[k * 64 + n];
        __nv_bfloat16 h = __float2bfloat16_rn(w);
        __nv_bfloat16 l = __float2bfloat16_rn(w - __bfloat162float(h));
        uint32_t off = (uint32_t)n * 144u + 2u * (uint32_t)k;
        *(__nv_bfloat16*)(g_B2hi + off) = h;
        *(__nv_bfloat16*)(g_B2lo + off) = l;
    }
}

// ---------------- k_pre: P[n] = y[n] @ [W1_top | W1_bot] (+b1 top) ----------------
#define PRE_SMEM_BYTES (37632 + 8 * 4608)
__global__ __launch_bounds__(256, 3)
void k_pre(const float* __restrict__ b1, const float* __restrict__ bg,
           const float* __restrict__ bb, int apply) {
    extern __shared__ unsigned char sm[];
    const uint32_t O_BPH = 0, O_BPL = 18432, O_B1B = 36864;
    const uint32_t O_BNS = 37120, O_BNB = 37376, O_WARP = 37632;
    const uint32_t S_AH = 0, S_AL = 2304;

    uint32_t sb = smem_u32(sm);
    int tid = threadIdx.x;
    int w = tid >> 5, l = tid & 31;

    float* sB1f = (float*)(sm + O_B1B);
    float* sSc = (float*)(sm + O_BNS);
    float* sBi = (float*)(sm + O_BNB);
    if (tid < 64) {
        sB1f[tid] = b1[tid];
        if (apply) {
            const float invn = 1.f / (float)N_NODES;
            float m = g_stats[tid] * invn;
            float var = g_stats[64 + tid] * invn - m * m;
            float sc = rsqrtf(var + BN_EPS) * bg[tid];
            sSc[tid] = sc;
            sBi[tid] = bb[tid] - m * sc;
        } else { sSc[tid] = 1.f; sBi[tid] = 0.f; }
    }
    {
        const float4* s; float4* d;
        s = (const float4*)g_BPhi; d = (float4*)(sm + O_BPH);
        for (int i = tid; i < 1152; i += 256) d[i] = s[i];
        s = (const float4*)g_BPlo; d = (float4*)(sm + O_BPL);
        for (int i = tid; i < 1152; i += 256) d[i] = s[i];
    }
    __syncthreads();

    unsigned char* wbp = sm + O_WARP + (uint32_t)w * 4608u;
    uint32_t wb = sb + O_WARP + (uint32_t)w * 4608u;

    int e = l >> 1, q = l & 1;
    uint32_t arow = (uint32_t)((l & 7) + ((l >> 3) & 1) * 8);
    uint32_t acol = (uint32_t)(l >> 4) * 16u;
    uint32_t brow = (uint32_t)((l & 7) + ((l >> 3) & 2) * 4);
    uint32_t bk = (uint32_t)((l >> 3) & 1) * 16u;

    int gw = blockIdx.x * 8 + w;
    int nw = gridDim.x * 8;

    for (int ch = gw; ch < N_NODES / 16; ch += nw) {
        int nbase = ch * 16;
        {
            const float4* hp = (const float4*)(g_h + (size_t)(nbase + e) * 64 + q * 32);
            uint32_t bo = S_AH + (uint32_t)e * 144u + (uint32_t)q * 64u;
            int cb = q * 32;
#pragma unroll
            for (int i = 0; i < 8; i++) {
                float4 v = hp[i];
                if (apply) {
                    int c = cb + 4 * i;
                    v.x = fmaxf(v.x * sSc[c + 0] + sBi[c + 0], 0.f);
                    v.y = fmaxf(v.y * sSc[c + 1] + sBi[c + 1], 0.f);
                    v.z = fmaxf(v.z * sSc[c + 2] + sBi[c + 2], 0.f);
                    v.w = fmaxf(v.w * sSc[c + 3] + sBi[c + 3], 0.f);
                }
                uint32_t h01, l01, h23, l23;
                split2(v.x, v.y, h01, l01);
                split2(v.z, v.w, h23, l23);
                *(uint2*)(wbp + bo + 8u * i) = make_uint2(h01, h23);
                *(uint2*)(wbp + bo + (S_AL - S_AH) + 8u * i) = make_uint2(l01, l23);
            }
        }
        __syncwarp();

        // prefetch next chunk's h line (deterministic address)
        {
            int chn = ch + nw;
            if (chn < N_NODES / 16)
                pf_l1(g_h + (size_t)(chn * 16 + e) * 64 + q * 32);
        }

        float d[16][4];
#pragma unroll
        for (int t = 0; t < 16; t++)
#pragma unroll
            for (int p = 0; p < 4; p++) d[t][p] = 0.f;
        {
            uint32_t aAh = wb + S_AH + arow * 144u + acol;
            uint32_t aAl = wb + S_AL + arow * 144u + acol;
            uint32_t aBh = sb + O_BPH + brow * 144u + bk;
            uint32_t aBl = sb + O_BPL + brow * 144u + bk;
#pragma unroll
            for (int ks = 0; ks < 4; ks++) {
                uint32_t ah[4], al[4];
                ldx4(ah, aAh + 32u * ks);
                ldx4(al, aAl + 32u * ks);
#pragma unroll
                for (int tp = 0; tp < 8; tp++) {
                    uint32_t bh[4], bl[4];
                    uint32_t toff = (uint32_t)tp * (16u * 144u) + 32u * ks;
                    ldx4(bh, aBh + toff);
                    ldx4(bl, aBl + toff);
                    mma16816(d[2 * tp],     ah, bh[0], bh[1]);
                    mma16816(d[2 * tp + 1], ah, bh[2], bh[3]);
                    mma16816(d[2 * tp],     al, bh[0], bh[1]);
                    mma16816(d[2 * tp + 1], al, bh[2], bh[3]);
                    mma16816(d[2 * tp],     ah, bl[0], bl[1]);
                    mma16816(d[2 * tp + 1], ah, bl[2], bl[3]);
                }
            }
        }

        {
            int r0 = l >> 2;
            int cc = 2 * (l & 3);
            float* P0 = g_P + (size_t)(nbase + r0) * 128;
            float* P1 = g_P + (size_t)(nbase + r0 + 8) * 128;
#pragma unroll
            for (int t = 0; t < 16; t++) {
                int c = 8 * t + cc;
                float ba = (c < 64) ? sB1f[c] : 0.f;
                float bb2 = (c < 64) ? sB1f[c + 1] : 0.f;
                *(float2*)(P0 + c) = make_float2(d[t][0] + ba, d[t][1] + bb2);
                *(float2*)(P1 + c) = make_float2(d[t][2] + ba, d[t][3] + bb2);
            }
        }
        __syncwarp();
    }
}

// ---------------- k_edge: GEMM2 + run-aggregated tanh RED; pipelined gather -------
#define EDGE_SMEM_BYTES (18688 + 8 * 4608)
__global__ __launch_bounds__(256, 3)
void k_edge(const float* __restrict__ b2) {
    extern __shared__ unsigned char sm[];
    const uint32_t O_B2H = 0, O_B2L = 9216, O_BI2 = 18432, O_WARP = 18688;
    const uint32_t S_A2H = 0, S_A2L = 2304, S_H2 = 0;

    uint32_t sb = smem_u32(sm);
    int tid = threadIdx.x;
    int w = tid >> 5, l = tid & 31;

    float* sB2f = (float*)(sm + O_BI2);
    if (tid < 64) sB2f[tid] = b2[tid];
    {
        const float4* s; float4* d;
        s = (const float4*)g_B2hi; d = (float4*)(sm + O_B2H);
        for (int i = tid; i < 576; i += 256) d[i] = s[i];
        s = (const float4*)g_B2lo; d = (float4*)(sm + O_B2L);
        for (int i = tid; i < 576; i += 256) d[i] = s[i];
    }
    __syncthreads();

    unsigned char* wbp = sm + O_WARP + (uint32_t)w * 4608u;
    uint32_t wb = sb + O_WARP + (uint32_t)w * 4608u;

    int e = l >> 1, q = l & 1;
    uint32_t arow = (uint32_t)((l & 7) + ((l >> 3) & 1) * 8);
    uint32_t acol = (uint32_t)(l >> 4) * 16u;
    uint32_t brow = (uint32_t)((l & 7) + ((l >> 3) & 2) * 4);
    uint32_t bk = (uint32_t)((l >> 3) & 1) * 16u;

    float b20 = sB2f[2 * l], b21 = sB2f[2 * l + 1];

    const int NC = N_EDGES / 16;
    int gw = blockIdx.x * 8 + w;
    int nw = gridDim.x * 8;

    int ch = gw;
    int dn = 0, sn = 0;
    if (ch < NC) {
        int ge = ch * 16 + e;
        dn = g_dst2[ge];
        sn = g_sd2[ge].x;
    }

    while (ch < NC) {
        // gather: hidden = relu(P_top[dn] + P_bot[sn]) -> bf16 hi/lo A2
        {
            const float4* pt = (const float4*)(g_P + (size_t)dn * 128 + q * 32);
            const float4* pbm = (const float4*)(g_P + (size_t)sn * 128 + 64 + q * 32);
            uint32_t bo = S_A2H + (uint32_t)e * 144u + (uint32_t)q * 64u;
#pragma unroll
            for (int i = 0; i < 8; i++) {
                float4 a = pt[i], b = pbm[i];
                float f0 = fmaxf(a.x + b.x, 0.f);
                float f1 = fmaxf(a.y + b.y, 0.f);
                float f2 = fmaxf(a.z + b.z, 0.f);
                float f3 = fmaxf(a.w + b.w, 0.f);
                uint32_t h01, l01, h23, l23;
                split2(f0, f1, h01, l01);
                split2(f2, f3, h23, l23);
                *(uint2*)(wbp + bo + 8u * i) = make_uint2(h01, h23);
                *(uint2*)(wbp + bo + (S_A2L - S_A2H) + 8u * i) = make_uint2(l01, l23);
            }
        }
        __syncwarp();

        // preload next chunk's indices + prefetch its P lines into L1
        int chn = ch + nw;
        int dnn = 0, snn = 0;
        if (chn < NC) {
            int ge2 = chn * 16 + e;
            dnn = g_dst2[ge2];
            snn = g_sd2[ge2].x;
            pf_l1(g_P + (size_t)dnn * 128 + q * 32);
            pf_l1(g_P + (size_t)snn * 128 + 64 + q * 32);
        }

        float d2[8][4];
#pragma unroll
        for (int t = 0; t < 8; t++)
#pragma unroll
            for (int p = 0; p < 4; p++) d2[t][p] = 0.f;
        {
            uint32_t aAh = wb + S_A2H + arow * 144u + acol;
            uint32_t aAl = wb + S_A2L + arow * 144u + acol;
            uint32_t aBh = sb + O_B2H + brow * 144u + bk;
            uint32_t aBl = sb + O_B2L + brow * 144u + bk;
#pragma unroll
            for (int ks = 0; ks < 4; ks++) {
                uint32_t ah[4], al[4];
                ldx4(ah, aAh + 32u * ks);
                ldx4(al, aAl + 32u * ks);
#pragma unroll
                for (int tp = 0; tp < 4; tp++) {
                    uint32_t bh[4], bl[4];
                    uint32_t toff = (uint32_t)tp * (16u * 144u) + 32u * ks;
                    ldx4(bh, aBh + toff);
                    ldx4(bl, aBl + toff);
                    mma16816(d2[2 * tp],     ah, bh[0], bh[1]);
                    mma16816(d2[2 * tp + 1], ah, bh[2], bh[3]);
                    mma16816(d2[2 * tp],     al, bh[0], bh[1]);
                    mma16816(d2[2 * tp + 1], al, bh[2], bh[3]);
                    mma16816(d2[2 * tp],     ah, bl[0], bl[1]);
                    mma16816(d2[2 * tp + 1], ah, bl[2], bl[3]);
                }
            }
        }
        __syncwarp();

        {
            int r0 = l >> 2;
            int cc = 2 * (l & 3);
#pragma unroll
            for (int t = 0; t < 8; t++) {
                int c = 8 * t + cc;
                *(float2*)(wbp + S_H2 + ((uint32_t)r0 * 66u + (uint32_t)c) * 4u)
                    = make_float2(d2[t][0], d2[t][1]);
                *(float2*)(wbp + S_H2 + ((uint32_t)(r0 + 8) * 66u + (uint32_t)c) * 4u)
                    = make_float2(d2[t][2], d2[t][3]);
            }
        }
        __syncwarp();

        // run-aggregated scatter: lane owns cols {2l, 2l+1}
        {
            const float* hbase = (const float*)(wbp + S_H2);
            float acc0 = 0.f, acc1 = 0.f;
            int prev = __shfl_sync(0xFFFFFFFFu, dn, 0);
#pragma unroll
            for (int e2 = 0; e2 < 16; e2++) {
                int dc = __shfl_sync(0xFFFFFFFFu, dn, 2 * e2);
                if (dc != prev) {
                    red2(g_msg + (size_t)prev * 64 + 2 * l, acc0, acc1);
                    acc0 = 0.f; acc1 = 0.f;
                    prev = dc;
                }
                float2 hv = *(const float2*)(hbase + e2 * 66 + 2 * l);
                acc0 += tanh_fast(hv.x + b20);
                acc1 += tanh_fast(hv.y + b21);
            }
            red2(g_msg + (size_t)prev * 64 + 2 * l, acc0, acc1);
        }
        __syncwarp();

        ch = chn; dn = dnn; sn = snn;
    }
}

// ---------------- node update: optional BN0+relu, then h *= (1+rdeg(2T-cnt)) ------
__global__ __launch_bounds__(256)
void k_update(int statOff, const float* __restrict__ bg,
              const float* __restrict__ bb, int apply, int zero_msg) {
    __shared__ float sSc[64], sBi[64];
    float* stats = g_stats + statOff;
    int tid = threadIdx.x;
    if (tid < 64) {
        if (apply) {
            const float invn = 1.f / (float)N_NODES;
            float m = g_stats[tid] * invn;
            float var = g_stats[64 + tid] * invn - m * m;
            float sc = rsqrtf(var + BN_EPS) * bg[tid];
            sSc[tid] = sc;
            sBi[tid] = bb[tid] - m * sc;
        } else { sSc[tid] = 1.f; sBi[tid] = 0.f; }
    }
    __syncthreads();

    int base = blockIdx.x * 4096;
    int c0 = (tid & 15) * 4;
    float4* h4 = (float4*)g_h;
    float4* m4 = (float4*)g_msg;
    float sc0 = sSc[c0], sc1 = sSc[c0 + 1], sc2 = sSc[c0 + 2], sc3 = sSc[c0 + 3];
    float bi0 = sBi[c0], bi1 = sBi[c0 + 1], bi2 = sBi[c0 + 2], bi3 = sBi[c0 + 3];
    float s[4] = {0.f, 0.f, 0.f, 0.f}, ss[4] = {0.f, 0.f, 0.f, 0.f};
#pragma unroll 4
    for (int i = 0; i < 16; i++) {
        int idx = base + tid + i * 256;
        if (idx < N_NODES * 16) {
            int n = idx >> 4;
            float rdeg = g_rdeg[n];
            float cnt = (float)g_cnt[n];
            float4 hv = h4[idx];
            float4 mv = m4[idx];
            if (apply) {
                hv.x = fmaxf(hv.x * sc0 + bi0, 0.f);
                hv.y = fmaxf(hv.y * sc1 + bi1, 0.f);
                hv.z = fmaxf(hv.z * sc2 + bi2, 0.f);
                hv.w = fmaxf(hv.w * sc3 + bi3, 0.f);
            }
            hv.x *= 1.f + rdeg * (2.f * mv.x - cnt);
            hv.y *= 1.f + rdeg * (2.f * mv.y - cnt);
            hv.z *= 1.f + rdeg * (2.f * mv.z - cnt);
            hv.w *= 1.f + rdeg * (2.f * mv.w - cnt);
            h4[idx] = hv;
            if (zero_msg) m4[idx] = make_float4(0.f, 0.f, 0.f, 0.f);
            s[0] += hv.x; s[1] += hv.y; s[2] += hv.z; s[3] += hv.w;
            ss[0] += hv.x * hv.x; ss[1] += hv.y * hv.y;
            ss[2] += hv.z * hv.z; ss[3] += hv.w * hv.w;
        }
    }
    __shared__ float sA[256][4], sBm[256][4];
#pragma unroll
    for (int p = 0; p < 4; p++) { sA[tid][p] = s[p]; sBm[tid][p] = ss[p]; }
    __syncthreads();
    if (tid < 16) {
        float rs[4] = {0.f, 0.f, 0.f, 0.f}, rss[4] = {0.f, 0.f, 0.f, 0.f};
#pragma unroll
        for (int j = 0; j < 16; j++) {
#pragma unroll
            for (int p = 0; p < 4; p++) {
                rs[p] += sA[tid + 16 * j][p];
                rss[p] += sBm[tid + 16 * j][p];
            }
        }
        int cc = tid * 4;
#pragma unroll
        for (int p = 0; p < 4; p++) {
            atomicAdd(&stats[cc + p], rs[p]);
            atomicAdd(&stats[64 + cc + p], rss[p]);
        }
    }
}

// ---------------- classifier (clf1 fuses layer-1 BN+relu) ----------------
__global__ void k_clf1(const float* __restrict__ W, const float* __restrict__ b,
                       const float* __restrict__ g, const float* __restrict__ bb) {
    __shared__ float sW[4096], sB[64], sScale[64], sBias[64];
    int tid = threadIdx.x;
    for (int i = tid; i < 4096; i += 256) sW[i] = W[i];
    if (tid < 64) {
        sB[tid] = b[tid];
        const float invn = 1.f / (float)N_NODES;
        float m = g_stats[128 + tid] * invn;
        float var = g_stats[192 + tid] * invn - m * m;
        float sc = rsqrtf(var + BN_EPS) * g[tid];
        sScale[tid] = sc;
        sBias[tid] = bb[tid] - m * sc;
    }
    __syncthreads();
    int r = blockIdx.x * 256 + tid;
    if (r >= BATCH) return;
    float acc[64];
#pragma unroll
    for (int c = 0; c < 64; c++) acc[c] = sB[c];
#pragma unroll 1
    for (int k = 0; k < 64; k++) {
        float hk = fmaxf(g_h[(size_t)r * 64 + k] * sScale[k] + sBias[k], 0.f);
        const float* w = &sW[k * 64];
#pragma unroll
        for (int c = 0; c < 64; c++) acc[c] += hk * w[c];
    }
    float* z = g_z1 + (size_t)r * 64;
    float* st = g_stats + 256;
#pragma unroll 1
    for (int c = 0; c < 64; c++) {
        z[c] = acc[c];
        atomicAdd(&st[c], acc[c]);
        atomicAdd(&st[64 + c], acc[c] * acc[c]);
    }
}

__global__ void k_clf2(const float* __restrict__ W, const float* __restrict__ b,
                       const float* __restrict__ g1, const float* __restrict__ bb1) {
    __shared__ float sW[2048], sB[32], sScale[64], sBias[64];
    int tid = threadIdx.x;
    for (int i = tid; i < 2048; i += 256) sW[i] = W[i];
    if (tid < 32) sB[tid] = b[tid];
    if (tid < 64) {
        const float invn = 1.f / (float)BATCH;
        float m = g_stats[256 + tid] * invn;
        float var = g_stats[256 + 64 + tid] * invn - m * m;
        float sc = rsqrtf(var + BN_EPS) * g1[tid];
        sScale[tid] = sc;
        sBias[tid] = bb1[tid] - m * sc;
    }
    __syncthreads();
    int r = blockIdx.x * 256 + tid;
    if (r >= BATCH) return;
    float acc[32];
#pragma unroll
    for (int c = 0; c < 32; c++) acc[c] = sB[c];
#pragma unroll 1
    for (int k = 0; k < 64; k++) {
        float v = fmaxf(g_z1[(size_t)r * 64 + k] * sScale[k] + sBias[k], 0.f);
        const float* w = &sW[k * 32];
#pragma unroll
        for (int c = 0; c < 32; c++) acc[c] += v * w[c];
    }
    float* z = g_z2 + (size_t)r * 32;
    float* st = g_stats + 384;
#pragma unroll 1
    for (int c = 0; c < 32; c++) {
        z[c] = acc[c];
        atomicAdd(&st[c], acc[c]);
        atomicAdd(&st[32 + c], acc[c] * acc[c]);
    }
}

__global__ void k_clf3(const float* __restrict__ W3, const float* __restrict__ b3,
                       const float* __restrict__ g2, const float* __restrict__ bb2,
                       float* __restrict__ out) {
    __shared__ float sW[32], sScale[32], sBias[32], sb3;
    int tid = threadIdx.x;
    if (tid < 32) {
        sW[tid] = W3[tid];
        const float invn = 1.f / (float)BATCH;
        float m = g_stats[384 + tid] * invn;
        float var = g_stats[384 + 32 + tid] * invn - m * m;
        float sc = rsqrtf(var + BN_EPS) * g2[tid];
        sScale[tid] = sc;
        sBias[tid] = bb2[tid] - m * sc;
    }
    if (tid == 0) sb3 = b3[0];
    __syncthreads();
    int r = blockIdx.x * 256 + tid;
    if (r >= BATCH) return;
    float a = sb3;
#pragma unroll 1
    for (int k = 0; k < 32; k++)
        a += fmaxf(g_z2[(size_t)r * 32 + k] * sScale[k] + sBias[k], 0.f) * sW[k];
    out[r] = a;
}

// ---------------- launch ----------------
extern "C" void kernel_launch(void* const* d_in, const int* in_sizes, int n_in,
                              void* d_out, int out_size) {
    auto ix = [&](int i) { return (n_in >= 28) ? i : (i > 3 ? i - 1 : i); };
    const float* x    = (const float*)d_in[ix(0)];
    const void*  ei   = d_in[ix(1)];
    const float* dts  = (const float*)d_in[ix(2)];
    const float* bf   = (const float*)d_in[ix(4)];
    const float* ph   = (const float*)d_in[ix(5)];
    const float* tW1  = (const float*)d_in[ix(6)];
    const float* tb1  = (const float*)d_in[ix(7)];
    const float* tW2  = (const float*)d_in[ix(8)];
    const float* tb2  = (const float*)d_in[ix(9)];
    const float* pW   = (const float*)d_in[ix(10)];
    const float* pb   = (const float*)d_in[ix(11)];
    const float* sW1  = (const float*)d_in[ix(12)];
    const float* sb1  = (const float*)d_in[ix(13)];
    const float* sW2  = (const float*)d_in[ix(14)];
    const float* sb2  = (const float*)d_in[ix(15)];
    const float* bng  = (const float*)d_in[ix(16)];
    const float* bnb  = (const float*)d_in[ix(17)];
    const float* cW1  = (const float*)d_in[ix(18)];
    const float* cb1  = (const float*)d_in[ix(19)];
    const float* cg1  = (const float*)d_in[ix(20)];
    const float* cbb1 = (const float*)d_in[ix(21)];
    const float* cW2  = (const float*)d_in[ix(22)];
    const float* cb2  = (const float*)d_in[ix(23)];
    const float* cg2  = (const float*)d_in[ix(24)];
    const float* cbb2 = (const float*)d_in[ix(25)];
    const float* cW3  = (const float*)d_in[ix(26)];
    const float* cb3  = (const float*)d_in[ix(27)];
    float* out = (float*)d_out;

    cudaFuncSetAttribute(k_pre, cudaFuncAttributeMaxDynamicSharedMemorySize, PRE_SMEM_BYTES);
    cudaFuncSetAttribute(k_edge, cudaFuncAttributeMaxDynamicSharedMemorySize, EDGE_SMEM_BYTES);

    k_zero_all<<<1024, 256>>>();
    k_pre1<<<(N_NODES + 127) / 128, 256>>>(x, tW1, tb1);
    k_convert_idx<<<N_EDGES / 256, 256>>>(ei);
    k_scan1<<<NSCAN_B, 256>>>();
    k_scan2<<<1, 512>>>();
    k_scan3<<<NSCAN_B, 256>>>();
    k_scatter<<<N_EDGES / 256, 256>>>(dts);
    k_stage1<<<N_EDGES / 512, 256>>>(bf, ph, tW1, tW2, tb2);
    k_proj<<<(N_NODES + 127) / 128, 256>>>(x, pW, pb);

    for (int l = 0; l < 2; l++) {
        k_prep_w<<<32, 256>>>(sW1 + l * 8192, sW2 + l * 4096);
        k_pre<<<444, 256, PRE_SMEM_BYTES>>>(sb1 + l * 64, bng, bnb, l);
        k_edge<<<444, 256, EDGE_SMEM_BYTES>>>(sb2 + l * 64);
        k_update<<<(N_NODES * 16 + 4095) / 4096, 256>>>(l * 128, bng, bnb, l, l == 0);
    }

    k_clf1<<<(BATCH + 255) / 256, 256>>>(cW1, cb1, bng + 64, bnb + 64);
    k_clf2<<<(BATCH + 255) / 256, 256>>>(cW2, cb2, cg1, cbb1);
    k_clf3<<<(BATCH + 255) / 256, 256>>>(cW3, cb3, cg2, cbb2, out);
    (void)in_sizes; (void)out_size;
}

// round 16
// speedup vs baseline: 1.0509x; 1.0509x over previous
#include <cuda_runtime.h>
#include <cuda_bf16.h>
#include <cstdint>

#define N_NODES 100000
#define N_EDGES 1600000
#define IN_CH   17
#define HID     64
#define BATCH   10000
#define BN_EPS  1e-5f
#define NSCAN_B 391

typedef unsigned long long ull;

// ---------------- device scratch ----------------
__device__ float g_h  [(size_t)N_NODES * HID];
__device__ float g_msg[(size_t)N_NODES * HID];   // accumulates T = sum of tanh
__device__ float g_P  [(size_t)N_NODES * 128];   // per-node GEMM1 precompute (stage-2)
__device__ float g_P12[(size_t)N_NODES * 68];    // stage-1 precompute
__device__ int   g_cnt[N_NODES];                 // in-degree (int)
__device__ int   g_cur[N_NODES];                 // scatter cursors
__device__ int   g_bsum[NSCAN_B];
__device__ int   g_boff[NSCAN_B];
__device__ float g_rdeg[N_NODES];
__device__ float g_stats[4 * 128];
__device__ float g_z1[BATCH * 64];
__device__ float g_z2[BATCH * 32];
__device__ int   g_src[N_EDGES];
__device__ int   g_dst[N_EDGES];
__device__ int   g_dst2[N_EDGES];                // sorted by dst
__device__ int2  g_sd2[N_EDGES];                 // (src, dts-bits) sorted by dst
// pre-packed bf16 hi/lo weight images (W^T row-major [n][k], row stride 144B)
__device__ __align__(16) unsigned char g_BPhi[128 * 144];
__device__ __align__(16) unsigned char g_BPlo[128 * 144];
__device__ __align__(16) unsigned char g_B2hi[64 * 144];
__device__ __align__(16) unsigned char g_B2lo[64 * 144];

__device__ __forceinline__ float tanh_fast(float x) {
    float e = __expf(2.f * x);
    return 1.f - __fdividef(2.f, e + 1.f);
}
__device__ __forceinline__ ull pack2(float x) {
    ull r; asm("mov.b64 %0,{%1,%1};" : "=l"(r) : "f"(x)); return r;
}
__device__ __forceinline__ void unpack2(ull a, float& x, float& y) {
    asm("mov.b64 {%0,%1},%2;" : "=f"(x), "=f"(y) : "l"(a));
}
__device__ __forceinline__ void fma2(ull& d, ull a, ull b) {
    asm("fma.rn.f32x2 %0,%1,%2,%0;" : "+l"(d) : "l"(a), "l"(b));
}
__device__ __forceinline__ ull add2(ull a, ull b) {
    ull r; asm("add.rn.f32x2 %0,%1,%2;" : "=l"(r) : "l"(a), "l"(b)); return r;
}
__device__ __forceinline__ void red4(float* p, float a, float b, float c, float d) {
    asm volatile("{\n\t.reg .u64 q;\n\tcvta.to.global.u64 q,%0;\n\t"
                 "red.global.add.v4.f32 [q],{%1,%2,%3,%4};\n\t}"
                 :: "l"(p), "f"(a), "f"(b), "f"(c), "f"(d) : "memory");
}
__device__ __forceinline__ void red2(float* p, float a, float b) {
    asm volatile("{\n\t.reg .u64 q;\n\tcvta.to.global.u64 q,%0;\n\t"
                 "red.global.add.v2.f32 [q],{%1,%2};\n\t}"
                 :: "l"(p), "f"(a), "f"(b) : "memory");
}
__device__ __forceinline__ uint32_t smem_u32(const void* p) {
    uint32_t a;
    asm("{.reg .u64 t; cvta.to.shared.u64 t, %1; cvt.u32.u64 %0, t;}" : "=r"(a) : "l"(p));
    return a;
}
__device__ __forceinline__ void ldx4(uint32_t* r, uint32_t a) {
    asm volatile("ldmatrix.sync.aligned.m8n8.x4.shared.b16 {%0,%1,%2,%3}, [%4];"
                 : "=r"(r[0]), "=r"(r[1]), "=r"(r[2]), "=r"(r[3]) : "r"(a));
}
__device__ __forceinline__ void mma16816(float* d, const uint32_t* a, uint32_t b0, uint32_t b1) {
    asm volatile("mma.sync.aligned.m16n8k16.row.col.f32.bf16.bf16.f32 "
                 "{%0,%1,%2,%3},{%4,%5,%6,%7},{%8,%9},{%0,%1,%2,%3};"
                 : "+f"(d[0]), "+f"(d[1]), "+f"(d[2]), "+f"(d[3])
                 : "r"(a[0]), "r"(a[1]), "r"(a[2]), "r"(a[3]), "r"(b0), "r"(b1));
}
__device__ __forceinline__ void split2(float x, float y, uint32_t& hi, uint32_t& lo) {
    __nv_bfloat162 h = __float22bfloat162_rn(make_float2(x, y));
    float2 hf = __bfloat1622float2(h);
    __nv_bfloat162 l = __float22bfloat162_rn(make_float2(x - hf.x, y - hf.y));
    hi = *(uint32_t*)&h; lo = *(uint32_t*)&l;
}

// ---------------- zero scratch ----------------
__global__ void k_zero_all() {
    int i = blockIdx.x * 256 + threadIdx.x;
    int st = gridDim.x * 256;
    float4 z = make_float4(0.f, 0.f, 0.f, 0.f);
    float4* m4 = (float4*)g_msg;
    for (int k = i; k < N_NODES * HID / 4; k += st) m4[k] = z;
    for (int k = i; k < N_NODES; k += st) g_cnt[k] = 0;
    if (i < 512) g_stats[i] = 0.f;
}

// ---------------- stage-1 node precompute ----------------
__global__ __launch_bounds__(256)
void k_pre1(const float* __restrict__ x, const float* __restrict__ W1,
            const float* __restrict__ b1) {
    __shared__ float sW[34 * 36];
    __shared__ __align__(8) float sB[34];
    int tid = threadIdx.x;
    for (int i = tid; i < 34 * 33; i += 256) {
        int r = i / 33, c = i - r * 33;
        sW[r * 36 + c] = W1[i];
    }
    if (tid < 33) sB[tid] = b1[tid];
    if (tid == 33) sB[33] = 0.f;
    __syncthreads();

    int n = blockIdx.x * 128 + (tid >> 1);
    int q = tid & 1;
    if (n >= N_NODES) return;

    ull acc[16];
    float t;
    if (q == 0) {
        const ull* bp = (const ull*)sB;
#pragma unroll
        for (int p = 0; p < 16; p++) acc[p] = bp[p];
        t = sB[32];
    } else {
#pragma unroll
        for (int p = 0; p < 16; p++) acc[p] = 0ull;
        t = 0.f;
    }

    const float* xp = x + (size_t)n * IN_CH;
#pragma unroll 1
    for (int i = 0; i < 17; i++) {
        float v = xp[i];
        ull m = pack2(v);
        const ulonglong2* wp = (const ulonglong2*)(sW + (17 * q + i) * 36);
#pragma unroll
        for (int h = 0; h < 8; h++) {
            ulonglong2 w = wp[h];
            fma2(acc[2 * h], m, w.x);
            fma2(acc[2 * h + 1], m, w.y);
        }
        t = fmaf(v, sW[(17 * q + i) * 36 + 32], t);
    }

    float* P = g_P12 + (size_t)n * 68 + 34 * q;
#pragma unroll
    for (int p = 0; p < 16; p++) {
        float a, b;
        unpack2(acc[p], a, b);
        *(float2*)(P + 2 * p) = make_float2(a, b);
    }
    P[32] = t;
}

// ---------------- edge index conversion + int degree ----------------
__global__ void k_convert_idx(const void* __restrict__ ei_raw) {
    __shared__ int s_is64;
    if (threadIdx.x == 0) {
        const unsigned* w = (const unsigned*)ei_raw;
        int is64 = 1;
        for (int i = 1; i < 64; i += 2)
            if (w[i] != 0u) { is64 = 0; break; }
        s_is64 = is64;
    }
    __syncthreads();
    int e = blockIdx.x * 256 + threadIdx.x;
    if (e >= N_EDGES) return;
    int s, d;
    if (s_is64) {
        const long long* p = (const long long*)ei_raw;
        s = (int)p[e]; d = (int)p[(size_t)N_EDGES + e];
    } else {
        const int* p = (const int*)ei_raw;
        s = p[e]; d = p[N_EDGES + e];
    }
    g_src[e] = s; g_dst[e] = d;
    atomicAdd(&g_cnt[d], 1);
}

// ---------------- 3-phase scan ----------------
__global__ __launch_bounds__(256)
void k_scan1() {
    __shared__ int sp[8];
    int n = blockIdx.x * 256 + threadIdx.x;
    int v = (n < N_NODES) ? g_cnt[n] : 0;
#pragma unroll
    for (int o = 16; o > 0; o >>= 1) v += __shfl_down_sync(0xFFFFFFFFu, v, o);
    if ((threadIdx.x & 31) == 0) sp[threadIdx.x >> 5] = v;
    __syncthreads();
    if (threadIdx.x == 0) {
        int s = 0;
#pragma unroll
        for (int i = 0; i < 8; i++) s += sp[i];
        g_bsum[blockIdx.x] = s;
    }
}
__global__ __launch_bounds__(512)
void k_scan2() {
    __shared__ int arr[512];
    int t = threadIdx.x;
    int v = (t < NSCAN_B) ? g_bsum[t] : 0;
    arr[t] = v;
    __syncthreads();
#pragma unroll
    for (int d = 1; d < 512; d <<= 1) {
        int u = (t >= d) ? arr[t - d] : 0;
        __syncthreads();
        arr[t] += u;
        __syncthreads();
    }
    if (t < NSCAN_B) g_boff[t] = arr[t] - v;
}
__global__ __launch_bounds__(256)
void k_scan3() {
    __shared__ int arr[256];
    int t = threadIdx.x;
    int n = blockIdx.x * 256 + t;
    int v = (n < N_NODES) ? g_cnt[n] : 0;
    arr[t] = v;
    __syncthreads();
#pragma unroll
    for (int d = 1; d < 256; d <<= 1) {
        int u = (t >= d) ? arr[t - d] : 0;
        __syncthreads();
        arr[t] += u;
        __syncthreads();
    }
    if (n < N_NODES) {
        g_cur[n] = g_boff[blockIdx.x] + arr[t] - v;
        g_rdeg[n] = 1.f / fmaxf((float)v, 1.f);
    }
}

// ---------------- scatter edges into dst-sorted order ----------------
__global__ void k_scatter(const float* __restrict__ dts) {
    int e = blockIdx.x * 256 + threadIdx.x;
    if (e >= N_EDGES) return;
    int d = g_dst[e];
    int pos = atomicAdd(&g_cur[d], 1);
    g_dst2[pos] = d;
    g_sd2[pos] = make_int2(g_src[e], __float_as_int(dts[e]));
}

// ---------------- stage 1: paired consecutive edges; merge REDs when same dst ----
__global__ __launch_bounds__(256)
void k_stage1(const float* __restrict__ bf, const float* __restrict__ ph,
              const float* __restrict__ W1,
              const float* __restrict__ W2, const float* __restrict__ b2) {
    __shared__ float sW1[32 * 36];
    __shared__ float sW2[33 * 20];
    __shared__ __align__(16) float sB2[18], sF[32], sP[32];
    int tid = threadIdx.x;
    for (int i = tid; i < 32 * 33; i += 256) {
        int r = i / 33, c = i - r * 33;
        sW1[r * 36 + c] = W1[(34 + r) * 33 + c];
    }
    for (int i = tid; i < 33 * 17; i += 256) {
        int r = i / 17, c = i - r * 17;
        sW2[r * 20 + c] = W2[i];
    }
    if (tid < 17) sB2[tid] = b2[tid];
    if (tid < 32) { sF[tid] = bf[tid]; sP[tid] = ph[tid]; }
    __syncthreads();

    int idx = blockIdx.x * 256 + tid;
    int e0 = idx * 2, e1 = idx * 2 + 1;
    int2 sd0 = g_sd2[e0], sd1 = g_sd2[e1];
    int d0 = g_dst2[e0], d1 = g_dst2[e1];
    int s0 = sd0.x, s1 = sd1.x;
    float dt0 = __int_as_float(sd0.y), dt1 = __int_as_float(sd1.y);

    ull a0[16], a1[16];
    float t0, t1;
    {
        const ull* p1d0 = (const ull*)(g_P12 + (size_t)d0 * 68);
        const ull* p2s0 = (const ull*)(g_P12 + (size_t)s0 * 68 + 34);
        const ull* p1d1 = (const ull*)(g_P12 + (size_t)d1 * 68);
        const ull* p2s1 = (const ull*)(g_P12 + (size_t)s1 * 68 + 34);
#pragma unroll
        for (int p = 0; p < 16; p++) {
            a0[p] = add2(p1d0[p], p2s0[p]);
            a1[p] = add2(p1d1[p], p2s1[p]);
        }
        t0 = g_P12[(size_t)d0 * 68 + 32] + g_P12[(size_t)s0 * 68 + 66];
        t1 = g_P12[(size_t)d1 * 68 + 32] + g_P12[(size_t)s1 * 68 + 66];
    }

#pragma unroll 1
    for (int t = 0; t < 32; t++) {
        float f = sF[t], p = sP[t];
        float v0 = __cosf(dt0 * f + p);
        float v1 = __cosf(dt1 * f + p);
        ull m0 = pack2(v0), m1 = pack2(v1);
        const ulonglong2* wp = (const ulonglong2*)(sW1 + t * 36);
        ulonglong2 wa = wp[0], wb = wp[1], wc = wp[2], wd = wp[3];
        ulonglong2 we = wp[4], wf2 = wp[5], wg = wp[6], wh = wp[7];
        fma2(a0[0], m0, wa.x);  fma2(a1[0], m1, wa.x);
        fma2(a0[1], m0, wa.y);  fma2(a1[1], m1, wa.y);
        fma2(a0[2], m0, wb.x);  fma2(a1[2], m1, wb.x);
        fma2(a0[3], m0, wb.y);  fma2(a1[3], m1, wb.y);
        fma2(a0[4], m0, wc.x);  fma2(a1[4], m1, wc.x);
        fma2(a0[5], m0, wc.y);  fma2(a1[5], m1, wc.y);
        fma2(a0[6], m0, wd.x);  fma2(a1[6], m1, wd.x);
        fma2(a0[7], m0, wd.y);  fma2(a1[7], m1, wd.y);
        fma2(a0[8], m0, we.x);  fma2(a1[8], m1, we.x);
        fma2(a0[9], m0, we.y);  fma2(a1[9], m1, we.y);
        fma2(a0[10], m0, wf2.x); fma2(a1[10], m1, wf2.x);
        fma2(a0[11], m0, wf2.y); fma2(a1[11], m1, wf2.y);
        fma2(a0[12], m0, wg.x); fma2(a1[12], m1, wg.x);
        fma2(a0[13], m0, wg.y); fma2(a1[13], m1, wg.y);
        fma2(a0[14], m0, wh.x); fma2(a1[14], m1, wh.x);
        fma2(a0[15], m0, wh.y); fma2(a1[15], m1, wh.y);
        float ws = sW1[t * 36 + 32];
        t0 = fmaf(v0, ws, t0); t1 = fmaf(v1, ws, t1);
    }

    float h0[33], h1[33];
#pragma unroll
    for (int p = 0; p < 16; p++) {
        unpack2(a0[p], h0[2 * p], h0[2 * p + 1]);
        unpack2(a1[p], h1[2 * p], h1[2 * p + 1]);
    }
    h0[32] = t0; h1[32] = t1;
#pragma unroll
    for (int i = 0; i < 33; i++) { h0[i] = fmaxf(h0[i], 0.f); h1[i] = fmaxf(h1[i], 0.f); }

    ull c0[8], c1[8]; float q0, q1;
    {
        const ull* bp = (const ull*)sB2;
#pragma unroll
        for (int p = 0; p < 8; p++) { c0[p] = bp[p]; c1[p] = bp[p]; }
        q0 = sB2[16]; q1 = sB2[16];
    }
#pragma unroll 1
    for (int i = 0; i < 33; i++) {
        ull m0 = pack2(h0[i]), m1 = pack2(h1[i]);
        const ulonglong2* wp = (const ulonglong2*)(sW2 + i * 20);
        ulonglong2 wa = wp[0], wb = wp[1], wc = wp[2], wd = wp[3];
        fma2(c0[0], m0, wa.x); fma2(c1[0], m1, wa.x);
        fma2(c0[1], m0, wa.y); fma2(c1[1], m1, wa.y);
        fma2(c0[2], m0, wb.x); fma2(c1[2], m1, wb.x);
        fma2(c0[3], m0, wb.y); fma2(c1[3], m1, wb.y);
        fma2(c0[4], m0, wc.x); fma2(c1[4], m1, wc.x);
        fma2(c0[5], m0, wc.y); fma2(c1[5], m1, wc.y);
        fma2(c0[6], m0, wd.x); fma2(c1[6], m1, wd.x);
        fma2(c0[7], m0, wd.y); fma2(c1[7], m1, wd.y);
        float ws = sW2[i * 20 + 16];
        q0 = fmaf(h0[i], ws, q0); q1 = fmaf(h1[i], ws, q1);
    }

    float pv0[17], pv1[17];
#pragma unroll
    for (int p = 0; p < 8; p++) {
        unpack2(c0[p], pv0[2 * p], pv0[2 * p + 1]);
        unpack2(c1[p], pv1[2 * p], pv1[2 * p + 1]);
    }
    pv0[16] = q0; pv1[16] = q1;

    if (d0 == d1) {
        float m[17];
#pragma unroll
        for (int j = 0; j < 17; j++) m[j] = tanh_fast(pv0[j]) + tanh_fast(pv1[j]);
        float* base = g_msg + (size_t)d0 * 64;
        red4(base + 0, m[0], m[1], m[2], m[3]);
        red4(base + 4, m[4], m[5], m[6], m[7]);
        red4(base + 8, m[8], m[9], m[10], m[11]);
        red4(base + 12, m[12], m[13], m[14], m[15]);
        atomicAdd(base + 16, m[16]);
    } else {
        float m[17];
#pragma unroll
        for (int j = 0; j < 17; j++) m[j] = tanh_fast(pv0[j]);
        float* base = g_msg + (size_t)d0 * 64;
        red4(base + 0, m[0], m[1], m[2], m[3]);
        red4(base + 4, m[4], m[5], m[6], m[7]);
        red4(base + 8, m[8], m[9], m[10], m[11]);
        red4(base + 12, m[12], m[13], m[14], m[15]);
        atomicAdd(base + 16, m[16]);
#pragma unroll
        for (int j = 0; j < 17; j++) m[j] = tanh_fast(pv1[j]);
        base = g_msg + (size_t)d1 * 64;
        red4(base + 0, m[0], m[1], m[2], m[3]);
        red4(base + 4, m[4], m[5], m[6], m[7]);
        red4(base + 8, m[8], m[9], m[10], m[11]);
        red4(base + 12, m[12], m[13], m[14], m[15]);
        atomicAdd(base + 16, m[16]);
    }
}

// ---------------- node update + projection ----------------
__global__ __launch_bounds__(256)
void k_proj(const float* __restrict__ x, const float* __restrict__ PW,
            const float* __restrict__ Pb) {
    __shared__ float sW[17 * 64];
    __shared__ __align__(16) float sB[64];
    int tid = threadIdx.x;
    for (int i = tid; i < 17 * 64; i += 256) sW[i] = PW[i];
    if (tid < 64) sB[tid] = Pb[tid];
    __syncthreads();

    int n = blockIdx.x * 128 + (tid >> 1);
    int q = tid & 1;
    if (n >= N_NODES) return;
    float rdeg = g_rdeg[n];
    float cnt = (float)g_cnt[n];

    ull acc[16];
    {
        const ull* bp = (const ull*)(sB + 32 * q);
#pragma unroll
        for (int p = 0; p < 16; p++) acc[p] = bp[p];
    }

    const float* xp = x + (size_t)n * 17;
    float* mp = g_msg + (size_t)n * 64;

#pragma unroll 1
    for (int k = 0; k < 17; k++) {
        float fac = 1.f + rdeg * (2.f * mp[k] - cnt);
        float xm = xp[k] * fac;
        ull m = pack2(xm);
        const ulonglong2* wp = (const ulonglong2*)(sW + k * 64 + 32 * q);
#pragma unroll
        for (int h = 0; h < 8; h++) {
            ulonglong2 w = wp[h];
            fma2(acc[2 * h], m, w.x);
            fma2(acc[2 * h + 1], m, w.y);
        }
    }

    float* hp = g_h + (size_t)n * 64 + 32 * q;
#pragma unroll
    for (int h = 0; h < 8; h++) {
        float a, b2, c, d;
        unpack2(acc[2 * h], a, b2);
        unpack2(acc[2 * h + 1], c, d);
        *(float4*)(hp + 4 * h) = make_float4(a, b2, c, d);
    }
    if (q == 0) {
        float4 z = make_float4(0.f, 0.f, 0.f, 0.f);
        *(float4*)(mp + 0) = z; *(float4*)(mp + 4) = z;
        *(float4*)(mp + 8) = z; *(float4*)(mp + 12) = z;
        mp[16] = 0.f;
    }
}

// ---------------- weight prep ----------------
__global__ void k_prep_w(const float* __restrict__ W1, const float* __restrict__ W2) {
    int idx = blockIdx.x * 256 + threadIdx.x;
    if (idx < 8192) {
        int nn = idx >> 6, k = idx & 63;
        float w = (nn < 64) ? W1[k * 64 + nn] : W1[(64 + k) * 64 + (nn - 64)];
        __nv_bfloat16 h = __float2bfloat16_rn(w);
        __nv_bfloat16 l = __float2bfloat16_rn(w - __bfloat162float(h));
        uint32_t off = (uint32_t)nn * 144u + 2u * (uint32_t)k;
        *(__nv_bfloat16*)(g_BPhi + off) = h;
        *(__nv_bfloat16*)(g_BPlo + off) = l;
    }
    if (idx < 4096) {
        int n = idx >> 6, k = idx & 63;
        float w = W2[k * 64 + n];
        __nv_bfloat16 h = __float2bfloat16_rn(w);
        __nv_bfloat16 l = __float2bfloat16_rn(w - __bfloat162float(h));
        uint32_t off = (uint32_t)n * 144u + 2u * (uint32_t)k;
        *(__nv_bfloat16*)(g_B2hi + off) = h;
        *(__nv_bfloat16*)(g_B2lo + off) = l;
    }
}

// ---------------- k_pre: P[n] = y[n] @ [W1_top | W1_bot] (+b1 top) ----------------
#define PRE_SMEM_BYTES (37632 + 8 * 4608)
__global__ __launch_bounds__(256, 3)
void k_pre(const float* __restrict__ b1, const float* __restrict__ bg,
           const float* __restrict__ bb, int apply) {
    extern __shared__ unsigned char sm[];
    const uint32_t O_BPH = 0, O_BPL = 18432, O_B1B = 36864;
    const uint32_t O_BNS = 37120, O_BNB = 37376, O_WARP = 37632;
    const uint32_t S_AH = 0, S_AL = 2304;

    uint32_t sb = smem_u32(sm);
    int tid = threadIdx.x;
    int w = tid >> 5, l = tid & 31;

    float* sB1f = (float*)(sm + O_B1B);
    float* sSc = (float*)(sm + O_BNS);
    float* sBi = (float*)(sm + O_BNB);
    if (tid < 64) {
        sB1f[tid] = b1[tid];
        if (apply) {
            const float invn = 1.f / (float)N_NODES;
            float m = g_stats[tid] * invn;
            float var = g_stats[64 + tid] * invn - m * m;
            float sc = rsqrtf(var + BN_EPS) * bg[tid];
            sSc[tid] = sc;
            sBi[tid] = bb[tid] - m * sc;
        } else { sSc[tid] = 1.f; sBi[tid] = 0.f; }
    }
    {
        const float4* s; float4* d;
        s = (const float4*)g_BPhi; d = (float4*)(sm + O_BPH);
        for (int i = tid; i < 1152; i += 256) d[i] = s[i];
        s = (const float4*)g_BPlo; d = (float4*)(sm + O_BPL);
        for (int i = tid; i < 1152; i += 256) d[i] = s[i];
    }
    __syncthreads();

    unsigned char* wbp = sm + O_WARP + (uint32_t)w * 4608u;
    uint32_t wb = sb + O_WARP + (uint32_t)w * 4608u;

    int e = l >> 1, q = l & 1;
    uint32_t arow = (uint32_t)((l & 7) + ((l >> 3) & 1) * 8);
    uint32_t acol = (uint32_t)(l >> 4) * 16u;
    uint32_t brow = (uint32_t)((l & 7) + ((l >> 3) & 2) * 4);
    uint32_t bk = (uint32_t)((l >> 3) & 1) * 16u;

    int gw = blockIdx.x * 8 + w;
    int nw = gridDim.x * 8;

    for (int ch = gw; ch < N_NODES / 16; ch += nw) {
        int nbase = ch * 16;
        {
            const float4* hp = (const float4*)(g_h + (size_t)(nbase + e) * 64 + q * 32);
            uint32_t bo = S_AH + (uint32_t)e * 144u + (uint32_t)q * 64u;
            int cb = q * 32;
#pragma unroll
            for (int i = 0; i < 8; i++) {
                float4 v = hp[i];
                if (apply) {
                    int c = cb + 4 * i;
                    v.x = fmaxf(v.x * sSc[c + 0] + sBi[c + 0], 0.f);
                    v.y = fmaxf(v.y * sSc[c + 1] + sBi[c + 1], 0.f);
                    v.z = fmaxf(v.z * sSc[c + 2] + sBi[c + 2], 0.f);
                    v.w = fmaxf(v.w * sSc[c + 3] + sBi[c + 3], 0.f);
                }
                uint32_t h01, l01, h23, l23;
                split2(v.x, v.y, h01, l01);
                split2(v.z, v.w, h23, l23);
                *(uint2*)(wbp + bo + 8u * i) = make_uint2(h01, h23);
                *(uint2*)(wbp + bo + (S_AL - S_AH) + 8u * i) = make_uint2(l01, l23);
            }
        }
        __syncwarp();

        float d[16][4];
#pragma unroll
        for (int t = 0; t < 16; t++)
#pragma unroll
            for (int p = 0; p < 4; p++) d[t][p] = 0.f;
        {
            uint32_t aAh = wb + S_AH + arow * 144u + acol;
            uint32_t aAl = wb + S_AL + arow * 144u + acol;
            uint32_t aBh = sb + O_BPH + brow * 144u + bk;
            uint32_t aBl = sb + O_BPL + brow * 144u + bk;
#pragma unroll
            for (int ks = 0; ks < 4; ks++) {
                uint32_t ah[4], al[4];
                ldx4(ah, aAh + 32u * ks);
                ldx4(al, aAl + 32u * ks);
#pragma unroll
                for (int tp = 0; tp < 8; tp++) {
                    uint32_t bh[4], bl[4];
                    uint32_t toff = (uint32_t)tp * (16u * 144u) + 32u * ks;
                    ldx4(bh, aBh + toff);
                    ldx4(bl, aBl + toff);
                    mma16816(d[2 * tp],     ah, bh[0], bh[1]);
                    mma16816(d[2 * tp + 1], ah, bh[2], bh[3]);
                    mma16816(d[2 * tp],     al, bh[0], bh[1]);
                    mma16816(d[2 * tp + 1], al, bh[2], bh[3]);
                    mma16816(d[2 * tp],     ah, bl[0], bl[1]);
                    mma16816(d[2 * tp + 1], ah, bl[2], bl[3]);
                }
            }
        }

        {
            int r0 = l >> 2;
            int cc = 2 * (l & 3);
            float* P0 = g_P + (size_t)(nbase + r0) * 128;
            float* P1 = g_P + (size_t)(nbase + r0 + 8) * 128;
#pragma unroll
            for (int t = 0; t < 16; t++) {
                int c = 8 * t + cc;
                float ba = (c < 64) ? sB1f[c] : 0.f;
                float bb2 = (c < 64) ? sB1f[c + 1] : 0.f;
                *(float2*)(P0 + c) = make_float2(d[t][0] + ba, d[t][1] + bb2);
                *(float2*)(P1 + c) = make_float2(d[t][2] + ba, d[t][3] + bb2);
            }
        }
        __syncwarp();
    }
}

// ---------------- k_edge: coalesced gather + GEMM2 + run-aggregated tanh RED -----
#define EDGE_SMEM_BYTES (18688 + 8 * 4608)
__global__ __launch_bounds__(256, 3)
void k_edge(const float* __restrict__ b2) {
    extern __shared__ unsigned char sm[];
    const uint32_t O_B2H = 0, O_B2L = 9216, O_BI2 = 18432, O_WARP = 18688;
    const uint32_t S_A2H = 0, S_A2L = 2304, S_H2 = 0;

    uint32_t sb = smem_u32(sm);
    int tid = threadIdx.x;
    int w = tid >> 5, l = tid & 31;

    float* sB2f = (float*)(sm + O_BI2);
    if (tid < 64) sB2f[tid] = b2[tid];
    {
        const float4* s; float4* d;
        s = (const float4*)g_B2hi; d = (float4*)(sm + O_B2H);
        for (int i = tid; i < 576; i += 256) d[i] = s[i];
        s = (const float4*)g_B2lo; d = (float4*)(sm + O_B2L);
        for (int i = tid; i < 576; i += 256) d[i] = s[i];
    }
    __syncthreads();

    unsigned char* wbp = sm + O_WARP + (uint32_t)w * 4608u;
    uint32_t wb = sb + O_WARP + (uint32_t)w * 4608u;

    int e = l >> 1;                      // edge owned for index purposes
    int j = l & 15, hf = l >> 4;         // gather lane coords
    uint32_t arow = (uint32_t)((l & 7) + ((l >> 3) & 1) * 8);
    uint32_t acol = (uint32_t)(l >> 4) * 16u;
    uint32_t brow = (uint32_t)((l & 7) + ((l >> 3) & 2) * 4);
    uint32_t bk = (uint32_t)((l >> 3) & 1) * 16u;

    float b20 = sB2f[2 * l], b21 = sB2f[2 * l + 1];

    const int NC = N_EDGES / 16;
    int gw = blockIdx.x * 8 + w;
    int nw = gridDim.x * 8;

    for (int ch = gw; ch < NC; ch += nw) {
        int ge = ch * 16 + e;
        int dn = g_dst2[ge];
        int sn = g_sd2[ge].x;

        // coalesced gather: per iteration, process 2 edges; half-warp loads each
        // row's contiguous 256B half. hidden = relu(P_top[dst]+P_bot[src]).
#pragma unroll
        for (int it = 0; it < 8; it++) {
            int ep = 2 * it + hf;
            int dcur = __shfl_sync(0xFFFFFFFFu, dn, 2 * ep);
            int scur = __shfl_sync(0xFFFFFFFFu, sn, 2 * ep);
            float4 a = *(const float4*)(g_P + (size_t)dcur * 128 + 4 * j);
            float4 b = *(const float4*)(g_P + (size_t)scur * 128 + 64 + 4 * j);
            float f0 = fmaxf(a.x + b.x, 0.f);
            float f1 = fmaxf(a.y + b.y, 0.f);
            float f2 = fmaxf(a.z + b.z, 0.f);
            float f3 = fmaxf(a.w + b.w, 0.f);
            uint32_t h01, l01, h23, l23;
            split2(f0, f1, h01, l01);
            split2(f2, f3, h23, l23);
            uint32_t bo = (uint32_t)ep * 144u + 8u * (uint32_t)j;
            *(uint2*)(wbp + S_A2H + bo) = make_uint2(h01, h23);
            *(uint2*)(wbp + S_A2L + bo) = make_uint2(l01, l23);
        }
        __syncwarp();

        float d2[8][4];
#pragma unroll
        for (int t = 0; t < 8; t++)
#pragma unroll
            for (int p = 0; p < 4; p++) d2[t][p] = 0.f;
        {
            uint32_t aAh = wb + S_A2H + arow * 144u + acol;
            uint32_t aAl = wb + S_A2L + arow * 144u + acol;
            uint32_t aBh = sb + O_B2H + brow * 144u + bk;
            uint32_t aBl = sb + O_B2L + brow * 144u + bk;
#pragma unroll
            for (int ks = 0; ks < 4; ks++) {
                uint32_t ah[4], al[4];
                ldx4(ah, aAh + 32u * ks);
                ldx4(al, aAl + 32u * ks);
#pragma unroll
                for (int tp = 0; tp < 4; tp++) {
                    uint32_t bh[4], bl[4];
                    uint32_t toff = (uint32_t)tp * (16u * 144u) + 32u * ks;
                    ldx4(bh, aBh + toff);
                    ldx4(bl, aBl + toff);
                    mma16816(d2[2 * tp],     ah, bh[0], bh[1]);
                    mma16816(d2[2 * tp + 1], ah, bh[2], bh[3]);
                    mma16816(d2[2 * tp],     al, bh[0], bh[1]);
                    mma16816(d2[2 * tp + 1], al, bh[2], bh[3]);
                    mma16816(d2[2 * tp],     ah, bl[0], bl[1]);
                    mma16816(d2[2 * tp + 1], ah, bl[2], bl[3]);
                }
            }
        }
        __syncwarp();

        {
            int r0 = l >> 2;
            int cc = 2 * (l & 3);
#pragma unroll
            for (int t = 0; t < 8; t++) {
                int c = 8 * t + cc;
                *(float2*)(wbp + S_H2 + ((uint32_t)r0 * 66u + (uint32_t)c) * 4u)
                    = make_float2(d2[t][0], d2[t][1]);
                *(float2*)(wbp + S_H2 + ((uint32_t)(r0 + 8) * 66u + (uint32_t)c) * 4u)
                    = make_float2(d2[t][2], d2[t][3]);
            }
        }
        __syncwarp();

        // run-aggregated scatter: lane owns cols {2l, 2l+1}
        {
            const float* hbase = (const float*)(wbp + S_H2);
            float acc0 = 0.f, acc1 = 0.f;
            int prev = __shfl_sync(0xFFFFFFFFu, dn, 0);
#pragma unroll
            for (int e2 = 0; e2 < 16; e2++) {
                int dc = __shfl_sync(0xFFFFFFFFu, dn, 2 * e2);
                if (dc != prev) {
                    red2(g_msg + (size_t)prev * 64 + 2 * l, acc0, acc1);
                    acc0 = 0.f; acc1 = 0.f;
                    prev = dc;
                }
                float2 hv = *(const float2*)(hbase + e2 * 66 + 2 * l);
                acc0 += tanh_fast(hv.x + b20);
                acc1 += tanh_fast(hv.y + b21);
            }
            red2(g_msg + (size_t)prev * 64 + 2 * l, acc0, acc1);
        }
        __syncwarp();
    }
}

// ---------------- node update: optional BN0+relu, then h *= (1+rdeg(2T-cnt)) ------
__global__ __launch_bounds__(256)
void k_update(int statOff, const float* __restrict__ bg,
              const float* __restrict__ bb, int apply, int zero_msg) {
    __shared__ float sSc[64], sBi[64];
    float* stats = g_stats + statOff;
    int tid = threadIdx.x;
    if (tid < 64) {
        if (apply) {
            const float invn = 1.f / (float)N_NODES;
            float m = g_stats[tid] * invn;
            float var = g_stats[64 + tid] * invn - m * m;
            float sc = rsqrtf(var + BN_EPS) * bg[tid];
            sSc[tid] = sc;
            sBi[tid] = bb[tid] - m * sc;
        } else { sSc[tid] = 1.f; sBi[tid] = 0.f; }
    }
    __syncthreads();

    int base = blockIdx.x * 4096;
    int c0 = (tid & 15) * 4;
    float4* h4 = (float4*)g_h;
    float4* m4 = (float4*)g_msg;
    float sc0 = sSc[c0], sc1 = sSc[c0 + 1], sc2 = sSc[c0 + 2], sc3 = sSc[c0 + 3];
    float bi0 = sBi[c0], bi1 = sBi[c0 + 1], bi2 = sBi[c0 + 2], bi3 = sBi[c0 + 3];
    float s[4] = {0.f, 0.f, 0.f, 0.f}, ss[4] = {0.f, 0.f, 0.f, 0.f};
#pragma unroll 4
    for (int i = 0; i < 16; i++) {
        int idx = base + tid + i * 256;
        if (idx < N_NODES * 16) {
            int n = idx >> 4;
            float rdeg = g_rdeg[n];
            float cnt = (float)g_cnt[n];
            float4 hv = h4[idx];
            float4 mv = m4[idx];
            if (apply) {
                hv.x = fmaxf(hv.x * sc0 + bi0, 0.f);
                hv.y = fmaxf(hv.y * sc1 + bi1, 0.f);
                hv.z = fmaxf(hv.z * sc2 + bi2, 0.f);
                hv.w = fmaxf(hv.w * sc3 + bi3, 0.f);
            }
            hv.x *= 1.f + rdeg * (2.f * mv.x - cnt);
            hv.y *= 1.f + rdeg * (2.f * mv.y - cnt);
            hv.z *= 1.f + rdeg * (2.f * mv.z - cnt);
            hv.w *= 1.f + rdeg * (2.f * mv.w - cnt);
            h4[idx] = hv;
            if (zero_msg) m4[idx] = make_float4(0.f, 0.f, 0.f, 0.f);
            s[0] += hv.x; s[1] += hv.y; s[2] += hv.z; s[3] += hv.w;
            ss[0] += hv.x * hv.x; ss[1] += hv.y * hv.y;
            ss[2] += hv.z * hv.z; ss[3] += hv.w * hv.w;
        }
    }
    __shared__ float sA[256][4], sBm[256][4];
#pragma unroll
    for (int p = 0; p < 4; p++) { sA[tid][p] = s[p]; sBm[tid][p] = ss[p]; }
    __syncthreads();
    if (tid < 16) {
        float rs[4] = {0.f, 0.f, 0.f, 0.f}, rss[4] = {0.f, 0.f, 0.f, 0.f};
#pragma unroll
        for (int jj = 0; jj < 16; jj++) {
#pragma unroll
            for (int p = 0; p < 4; p++) {
                rs[p] += sA[tid + 16 * jj][p];
                rss[p] += sBm[tid + 16 * jj][p];
            }
        }
        int cc = tid * 4;
#pragma unroll
        for (int p = 0; p < 4; p++) {
            atomicAdd(&stats[cc + p], rs[p]);
            atomicAdd(&stats[64 + cc + p], rss[p]);
        }
    }
}

// ---------------- classifier (clf1 fuses layer-1 BN+relu) ----------------
__global__ void k_clf1(const float* __restrict__ W, const float* __restrict__ b,
                       const float* __restrict__ g, const float* __restrict__ bb) {
    __shared__ float sW[4096], sB[64], sScale[64], sBias[64];
    int tid = threadIdx.x;
    for (int i = tid; i < 4096; i += 256) sW[i] = W[i];
    if (tid < 64) {
        sB[tid] = b[tid];
        const float invn = 1.f / (float)N_NODES;
        float m = g_stats[128 + tid] * invn;
        float var = g_stats[192 + tid] * invn - m * m;
        float sc = rsqrtf(var + BN_EPS) * g[tid];
        sScale[tid] = sc;
        sBias[tid] = bb[tid] - m * sc;
    }
    __syncthreads();
    int r = blockIdx.x * 256 + tid;
    if (r >= BATCH) return;
    float acc[64];
#pragma unroll
    for (int c = 0; c < 64; c++) acc[c] = sB[c];
#pragma unroll 1
    for (int k = 0; k < 64; k++) {
        float hk = fmaxf(g_h[(size_t)r * 64 + k] * sScale[k] + sBias[k], 0.f);
        const float* w = &sW[k * 64];
#pragma unroll
        for (int c = 0; c < 64; c++) acc[c] += hk * w[c];
    }
    float* z = g_z1 + (size_t)r * 64;
    float* st = g_stats + 256;
#pragma unroll 1
    for (int c = 0; c < 64; c++) {
        z[c] = acc[c];
        atomicAdd(&st[c], acc[c]);
        atomicAdd(&st[64 + c], acc[c] * acc[c]);
    }
}

__global__ void k_clf2(const float* __restrict__ W, const float* __restrict__ b,
                       const float* __restrict__ g1, const float* __restrict__ bb1) {
    __shared__ float sW[2048], sB[32], sScale[64], sBias[64];
    int tid = threadIdx.x;
    for (int i = tid; i < 2048; i += 256) sW[i] = W[i];
    if (tid < 32) sB[tid] = b[tid];
    if (tid < 64) {
        const float invn = 1.f / (float)BATCH;
        float m = g_stats[256 + tid] * invn;
        float var = g_stats[256 + 64 + tid] * invn - m * m;
        float sc = rsqrtf(var + BN_EPS) * g1[tid];
        sScale[tid] = sc;
        sBias[tid] = bb1[tid] - m * sc;
    }
    __syncthreads();
    int r = blockIdx.x * 256 + tid;
    if (r >= BATCH) return;
    float acc[32];
#pragma unroll
    for (int c = 0; c < 32; c++) acc[c] = sB[c];
#pragma unroll 1
    for (int k = 0; k < 64; k++) {
        float v = fmaxf(g_z1[(size_t)r * 64 + k] * sScale[k] + sBias[k], 0.f);
        const float* w = &sW[k * 32];
#pragma unroll
        for (int c = 0; c < 32; c++) acc[c] += v * w[c];
    }
    float* z = g_z2 + (size_t)r * 32;
    float* st = g_stats + 384;
#pragma unroll 1
    for (int c = 0; c < 32; c++) {
        z[c] = acc[c];
        atomicAdd(&st[c], acc[c]);
        atomicAdd(&st[32 + c], acc[c] * acc[c]);
    }
}

__global__ void k_clf3(const float* __restrict__ W3, const float* __restrict__ b3,
                       const float* __restrict__ g2, const float* __restrict__ bb2,
                       float* __restrict__ out) {
    __shared__ float sW[32], sScale[32], sBias[32], sb3;
    int tid = threadIdx.x;
    if (tid < 32) {
        sW[tid] = W3[tid];
        const float invn = 1.f / (float)BATCH;
        float m = g_stats[384 + tid] * invn;
        float var = g_stats[384 + 32 + tid] * invn - m * m;
        float sc = rsqrtf(var + BN_EPS) * g2[tid];
        sScale[tid] = sc;
        sBias[tid] = bb2[tid] - m * sc;
    }
    if (tid == 0) sb3 = b3[0];
    __syncthreads();
    int r = blockIdx.x * 256 + tid;
    if (r >= BATCH) return;
    float a = sb3;
#pragma unroll 1
    for (int k = 0; k < 32; k++)
        a += fmaxf(g_z2[(size_t)r * 32 + k] * sScale[k] + sBias[k], 0.f) * sW[k];
    out[r] = a;
}

// ---------------- launch ----------------
extern "C" void kernel_launch(void* const* d_in, const int* in_sizes, int n_in,
                              void* d_out, int out_size) {
    auto ix = [&](int i) { return (n_in >= 28) ? i : (i > 3 ? i - 1 : i); };
    const float* x    = (const float*)d_in[ix(0)];
    const void*  ei   = d_in[ix(1)];
    const float* dts  = (const float*)d_in[ix(2)];
    const float* bf   = (const float*)d_in[ix(4)];
    const float* ph   = (const float*)d_in[ix(5)];
    const float* tW1  = (const float*)d_in[ix(6)];
    const float* tb1  = (const float*)d_in[ix(7)];
    const float* tW2  = (const float*)d_in[ix(8)];
    const float* tb2  = (const float*)d_in[ix(9)];
    const float* pW   = (const float*)d_in[ix(10)];
    const float* pb   = (const float*)d_in[ix(11)];
    const float* sW1  = (const float*)d_in[ix(12)];
    const float* sb1  = (const float*)d_in[ix(13)];
    const float* sW2  = (const float*)d_in[ix(14)];
    const float* sb2  = (const float*)d_in[ix(15)];
    const float* bng  = (const float*)d_in[ix(16)];
    const float* bnb  = (const float*)d_in[ix(17)];
    const float* cW1  = (const float*)d_in[ix(18)];
    const float* cb1  = (const float*)d_in[ix(19)];
    const float* cg1  = (const float*)d_in[ix(20)];
    const float* cbb1 = (const float*)d_in[ix(21)];
    const float* cW2  = (const float*)d_in[ix(22)];
    const float* cb2  = (const float*)d_in[ix(23)];
    const float* cg2  = (const float*)d_in[ix(24)];
    const float* cbb2 = (const float*)d_in[ix(25)];
    const float* cW3  = (const float*)d_in[ix(26)];
    const float* cb3  = (const float*)d_in[ix(27)];
    float* out = (float*)d_out;

    cudaFuncSetAttribute(k_pre, cudaFuncAttributeMaxDynamicSharedMemorySize, PRE_SMEM_BYTES);
    cudaFuncSetAttribute(k_edge, cudaFuncAttributeMaxDynamicSharedMemorySize, EDGE_SMEM_BYTES);

    k_zero_all<<<1024, 256>>>();
    k_pre1<<<(N_NODES + 127) / 128, 256>>>(x, tW1, tb1);
    k_convert_idx<<<N_EDGES / 256, 256>>>(ei);
    k_scan1<<<NSCAN_B, 256>>>();
    k_scan2<<<1, 512>>>();
    k_scan3<<<NSCAN_B, 256>>>();
    k_scatter<<<N_EDGES / 256, 256>>>(dts);
    k_stage1<<<N_EDGES / 512, 256>>>(bf, ph, tW1, tW2, tb2);
    k_proj<<<(N_NODES + 127) / 128, 256>>>(x, pW, pb);

    for (int l = 0; l < 2; l++) {
        k_prep_w<<<32, 256>>>(sW1 + l * 8192, sW2 + l * 4096);
        k_pre<<<444, 256, PRE_SMEM_BYTES>>>(sb1 + l * 64, bng, bnb, l);
        k_edge<<<444, 256, EDGE_SMEM_BYTES>>>(sb2 + l * 64);
        k_update<<<(N_NODES * 16 + 4095) / 4096, 256>>>(l * 128, bng, bnb, l, l == 0);
    }

    k_clf1<<<(BATCH + 255) / 256, 256>>>(cW1, cb1, bng + 64, bnb + 64);
    k_clf2<<<(BATCH + 255) / 256, 256>>>(cW2, cb2, cg1, cbb1);
    k_clf3<<<(BATCH + 255) / 256, 256>>>(cW3, cb3, cg2, cbb2, out);
    (void)in_sizes; (void)out_size;
}